// round 8
// baseline (speedup 1.0000x reference)
#include <cuda_runtime.h>
#include <cuda_bf16.h>
#include <cstdint>
#include <cstddef>
#include <math.h>

// Problem constants
#define NN   100000
#define FF   256
#define HH   64
#define CC   40
#define LL   4
#define EE   1200000
#define G3   192            // 3*H

// ---------------- scratch (__device__ globals; no allocation allowed) ------
__device__ __align__(16) float g_h   [NN * HH];       // hidden state
__device__ __align__(16) float g_S   [NN * HH];       // aggregated neighbor sum
// Stacked, column-permuted, split-bf16 GRU weight table:
// G[l][jj][k], jj in [0,192), k in [0,128):
//   t = (jj%96)/32, d = (jj/96)*32 + (jj%32), j = t*64 + d  (orig col)
//   k<64  -> Wp[j][k]  = sum_b conv_w[l][k][b] * w_ih[j][b]
//   k>=64 -> Whh[j][k-64] = w_hh[j][k-64]
__device__ __align__(16) __nv_bfloat16 g_GH[LL * G3 * 128];
__device__ __align__(16) __nv_bfloat16 g_GL[LL * G3 * 128];
__device__ int g_cnt   [NN];
__device__ int g_rowptr[NN + 1];
__device__ int g_cursor[NN];
__device__ int g_esrc  [EE];
__device__ int g_bsum  [64];
__device__ int g_boff  [64];
__device__ int g_fmt;          // 0 = int64 edge_index layout, 1 = int32 layout

// ---------------- mma.sync helper (baseline PTX, legal on compute_103) -----
__device__ __forceinline__ void mma16816(float* d, const uint32_t* a,
                                         const uint32_t* b) {
    asm volatile(
        "mma.sync.aligned.m16n8k16.row.col.f32.bf16.bf16.f32 "
        "{%0,%1,%2,%3}, {%4,%5,%6,%7}, {%8,%9}, {%0,%1,%2,%3};"
        : "+f"(d[0]), "+f"(d[1]), "+f"(d[2]), "+f"(d[3])
        : "r"(a[0]), "r"(a[1]), "r"(a[2]), "r"(a[3]), "r"(b[0]), "r"(b[1]));
}

// ---------------- edge dtype detection --------------------------------------
__global__ void k_zero_misc() {
    int i = blockIdx.x * blockDim.x + threadIdx.x;
    if (i < NN) g_cnt[i] = 0;
    if (i == 0) g_fmt = 0;
}

__global__ void k_detect(const int* __restrict__ ei32) {
    int i = blockIdx.x * blockDim.x + threadIdx.x;
    int v = 0;
    if (i < EE) v = ei32[2 * i + 1];
    if (__syncthreads_or(v != 0)) {
        if (threadIdx.x == 0) atomicOr(&g_fmt, 1);
    }
}

// ---------------- CSR construction -----------------------------------------
__device__ __forceinline__ int edge_src(const int* ei32, int e) {
    return g_fmt ? ei32[e] : ei32[2 * e];
}
__device__ __forceinline__ int edge_dst(const int* ei32, int e) {
    return g_fmt ? ei32[EE + e] : ei32[2 * EE + 2 * e];
}

__global__ void k_hist(const int* __restrict__ ei32) {
    int e = blockIdx.x * blockDim.x + threadIdx.x;
    if (e < EE) atomicAdd(&g_cnt[edge_dst(ei32, e)], 1);
}

__global__ void k_scan1() {
    __shared__ int red[256];
    int tid = threadIdx.x;
    int base = blockIdx.x * 2048 + tid * 8;
    int s = 0;
#pragma unroll
    for (int i = 0; i < 8; ++i) {
        int idx = base + i;
        s += (idx < NN) ? g_cnt[idx] : 0;
    }
    red[tid] = s;
    __syncthreads();
    for (int off = 128; off > 0; off >>= 1) {
        if (tid < off) red[tid] += red[tid + off];
        __syncthreads();
    }
    if (tid == 0) g_bsum[blockIdx.x] = red[0];
}

__global__ void k_scan2(int nb) {
    if (threadIdx.x == 0 && blockIdx.x == 0) {
        int run = 0;
        for (int b = 0; b < nb; ++b) {
            int t = g_bsum[b];
            g_boff[b] = run;
            run += t;
        }
        g_rowptr[NN] = run;
    }
}

__global__ void k_scan3() {
    __shared__ int sSum[256];
    int tid = threadIdx.x;
    int base = blockIdx.x * 2048 + tid * 8;
    int v[8];
    int s = 0;
#pragma unroll
    for (int i = 0; i < 8; ++i) {
        int idx = base + i;
        v[i] = (idx < NN) ? g_cnt[idx] : 0;
        s += v[i];
    }
    sSum[tid] = s;
    __syncthreads();
    for (int off = 1; off < 256; off <<= 1) {
        int t = (tid >= off) ? sSum[tid - off] : 0;
        __syncthreads();
        sSum[tid] += t;
        __syncthreads();
    }
    int excl = sSum[tid] - s + g_boff[blockIdx.x];
#pragma unroll
    for (int i = 0; i < 8; ++i) {
        int idx = base + i;
        if (idx < NN) {
            g_rowptr[idx] = excl;
            g_cursor[idx] = excl;
        }
        excl += v[i];
    }
}

__global__ void k_fill(const int* __restrict__ ei32) {
    int e = blockIdx.x * blockDim.x + threadIdx.x;
    if (e < EE) {
        int s = edge_src(ei32, e);
        int d = edge_dst(ei32, e);
        int pos = atomicAdd(&g_cursor[d], 1);
        g_esrc[pos] = s;
    }
}

// ---------------- fused weight precompute (stacked, permuted, split) --------
__global__ void k_wp(const float* __restrict__ conv_w,
                     const float* __restrict__ w_ih,
                     const float* __restrict__ w_hh) {
    int id = blockIdx.x * blockDim.x + threadIdx.x;
    if (id >= LL * G3 * 128) return;
    int l = id / (G3 * 128);
    int r = id % (G3 * 128);
    int jj = r / 128;
    int k = r % 128;
    int t = (jj % 96) / 32;
    int d = (jj / 96) * 32 + (jj % 32);
    int j = t * 64 + d;
    float s;
    if (k < 64) {
        const float* cw = conv_w + (l * HH + k) * HH;
        const float* wi = w_ih + j * HH;
        s = 0.f;
#pragma unroll 8
        for (int b = 0; b < HH; ++b) s += cw[b] * wi[b];
    } else {
        s = w_hh[j * HH + (k - 64)];
    }
    __nv_bfloat16 hi = __float2bfloat16(s);
    __nv_bfloat16 lo = __float2bfloat16(s - __bfloat162float(hi));
    g_GH[id] = hi;
    g_GL[id] = lo;
}

// ---------------- input GEMM: h = x @ W_in  [N,256]@[256,64] ----------------
__global__ void __launch_bounds__(256) k_ingemm(const float* __restrict__ x,
                                                const float* __restrict__ win) {
    __shared__ float sW[64 * 64];
    __shared__ float sX[64 * 64];
    int tid = threadIdx.x;
    int node0 = blockIdx.x * 64;

    int tn = tid >> 5;
    int tj = tid & 31;
    float acc[8][2];
#pragma unroll
    for (int i = 0; i < 8; ++i) { acc[i][0] = 0.f; acc[i][1] = 0.f; }

    for (int kc = 0; kc < 4; ++kc) {
        __syncthreads();
        {
            const float4* w4 = (const float4*)win;
            float4* d4 = (float4*)sW;
            for (int i = tid; i < 1024; i += 256) d4[i] = w4[kc * 1024 + i];
        }
        for (int i = tid; i < 1024; i += 256) {
            int n = i >> 4, c = i & 15;
            int node = node0 + n;
            float4 v = make_float4(0.f, 0.f, 0.f, 0.f);
            if (node < NN)
                v = *(const float4*)(x + (long)node * FF + kc * 64 + c * 4);
            ((float4*)sX)[i] = v;
        }
        __syncthreads();
        const float* sXr = sX + tn * 8 * 64;
#pragma unroll 8
        for (int kk = 0; kk < 64; ++kk) {
            float w0 = sW[kk * 64 + tj];
            float w1 = sW[kk * 64 + tj + 32];
#pragma unroll
            for (int i = 0; i < 8; ++i) {
                float a = sXr[i * 64 + kk];
                acc[i][0] += a * w0;
                acc[i][1] += a * w1;
            }
        }
    }
#pragma unroll
    for (int i = 0; i < 8; ++i) {
        int node = node0 + tn * 8 + i;
        if (node < NN) {
            g_h[node * HH + tj]      = acc[i][0];
            g_h[node * HH + tj + 32] = acc[i][1];
        }
    }
}

// ---------------- aggregation: S[v] = sum_{e:dst=v} h[src[e]] ---------------
__global__ void k_agg() {
    int warp = (blockIdx.x * blockDim.x + threadIdx.x) >> 5;
    int lane = threadIdx.x & 31;
    if (warp >= NN) return;
    int beg = g_rowptr[warp], end = g_rowptr[warp + 1];
    float a0 = 0.f, a1 = 0.f, b0 = 0.f, b1 = 0.f;
    int e = beg;
    for (; e + 1 < end; e += 2) {
        int s0 = g_esrc[e], s1 = g_esrc[e + 1];
        const float* h0 = g_h + (long)s0 * HH;
        const float* h1 = g_h + (long)s1 * HH;
        a0 += h0[lane];      a1 += h0[lane + 32];
        b0 += h1[lane];      b1 += h1[lane + 32];
    }
    if (e < end) {
        const float* h0 = g_h + (long)g_esrc[e] * HH;
        a0 += h0[lane];      a1 += h0[lane + 32];
    }
    g_S[warp * HH + lane]      = a0 + b0;
    g_S[warp * HH + lane + 32] = a1 + b1;
}

// ---------------- HMMA GRU layer --------------------------------------------
// 128-node tile, 512 threads (16 warps). A = [S | h] (K=128), W = g_G table.
// Warp w: rows rb*16..+15 (rb=w>>1), col group g=w&1 (96 GEMM cols).
// nb 0-3: r-gate dims, nb 4-7: z-gate, nb 8-11: n-gate (IN from S-chunks,
// HN from h-chunks kept in separate accumulators).
// Split-bf16 3 terms: Ah*Wh + Al*Wh + Ah*Wl.
#define ASTR 40   // A smem row stride (elems) — conflict-free
#define BSTR 36   // B smem row stride (elems)

__device__ __forceinline__ void split8s(const float* f, uint2* hi2, uint2* lo2) {
    unsigned int hw[4], lw[4];
#pragma unroll
    for (int i = 0; i < 4; ++i) {
        __nv_bfloat16 h0 = __float2bfloat16(f[2 * i]);
        __nv_bfloat16 h1 = __float2bfloat16(f[2 * i + 1]);
        __nv_bfloat16 l0 = __float2bfloat16(f[2 * i]     - __bfloat162float(h0));
        __nv_bfloat16 l1 = __float2bfloat16(f[2 * i + 1] - __bfloat162float(h1));
        hw[i] = (unsigned)__bfloat16_as_ushort(h0) | ((unsigned)__bfloat16_as_ushort(h1) << 16);
        lw[i] = (unsigned)__bfloat16_as_ushort(l0) | ((unsigned)__bfloat16_as_ushort(l1) << 16);
    }
    hi2[0] = make_uint2(hw[0], hw[1]); hi2[1] = make_uint2(hw[2], hw[3]);
    lo2[0] = make_uint2(lw[0], lw[1]); lo2[1] = make_uint2(lw[2], lw[3]);
}

__global__ void __launch_bounds__(512) k_gru_mma(const float* __restrict__ b_ih,
                                                 const float* __restrict__ b_hh,
                                                 int layer) {
    __shared__ __nv_bfloat16 sAh[128 * ASTR];   // 10240 B
    __shared__ __nv_bfloat16 sAl[128 * ASTR];   // 10240 B
    __shared__ __nv_bfloat16 sBh[G3 * BSTR];    // 13824 B
    __shared__ __nv_bfloat16 sBl[G3 * BSTR];    // 13824 B  (total 48128)
    int tid = threadIdx.x;
    int node0 = blockIdx.x * 128;

    int w = tid >> 5, lane = tid & 31;
    int rb = w >> 1, g = w & 1;
    int q = lane >> 2, c4 = lane & 3;

    float accRZ[8][4], accIN[4][4], accHN[4][4];
#pragma unroll
    for (int i = 0; i < 8; ++i)
#pragma unroll
        for (int j = 0; j < 4; ++j) accRZ[i][j] = 0.f;
#pragma unroll
    for (int i = 0; i < 4; ++i)
#pragma unroll
        for (int j = 0; j < 4; ++j) { accIN[i][j] = 0.f; accHN[i][j] = 0.f; }

    const __nv_bfloat16* GH = g_GH + (size_t)layer * G3 * 128;
    const __nv_bfloat16* GL = g_GL + (size_t)layer * G3 * 128;

    for (int kc = 0; kc < 4; ++kc) {
        __syncthreads();   // protect previous chunk's smem until all warps done
        // ---- stage A chunk: rows 0..127, cols kc*32..+31 of [S|h] ----
        {
            int row = tid >> 2;
            int c8 = (tid & 3) * 8;
            int node = node0 + row;
            float f[8];
            const float* src = (kc < 2) ? g_S : g_h;
            int cb = (kc & 1) * 32 + c8;
            if (node < NN) {
                float4 v0 = *(const float4*)(src + (long)node * HH + cb);
                float4 v1 = *(const float4*)(src + (long)node * HH + cb + 4);
                f[0] = v0.x; f[1] = v0.y; f[2] = v0.z; f[3] = v0.w;
                f[4] = v1.x; f[5] = v1.y; f[6] = v1.z; f[7] = v1.w;
            } else {
#pragma unroll
                for (int i = 0; i < 8; ++i) f[i] = 0.f;
            }
            uint2 hi2[2], lo2[2];
            split8s(f, hi2, lo2);
            uint2* dh = (uint2*)&sAh[row * ASTR + c8];
            uint2* dl = (uint2*)&sAl[row * ASTR + c8];
            dh[0] = hi2[0]; dh[1] = hi2[1];
            dl[0] = lo2[0]; dl[1] = lo2[1];
        }
        // ---- stage B chunk: 192 cols x 32 k ----
        for (int i = tid; i < G3 * 4; i += 512) {
            int j = i >> 2, kk8 = (i & 3) * 8;
            size_t src = (size_t)j * 128 + kc * 32 + kk8;
            uint4 vh = *(const uint4*)(GH + src);
            uint4 vl = *(const uint4*)(GL + src);
            uint2* dh = (uint2*)&sBh[j * BSTR + kk8];
            uint2* dl = (uint2*)&sBl[j * BSTR + kk8];
            dh[0] = make_uint2(vh.x, vh.y); dh[1] = make_uint2(vh.z, vh.w);
            dl[0] = make_uint2(vl.x, vl.y); dl[1] = make_uint2(vl.z, vl.w);
        }
        __syncthreads();

        // ---- compute: 2 k-steps of 16 ----
        int arow = rb * 16 + q;
#pragma unroll
        for (int ks = 0; ks < 2; ++ks) {
            int ac = ks * 16 + c4 * 2;
            uint32_t ah[4], al[4];
            ah[0] = *(const uint32_t*)&sAh[arow * ASTR + ac];
            ah[1] = *(const uint32_t*)&sAh[(arow + 8) * ASTR + ac];
            ah[2] = *(const uint32_t*)&sAh[arow * ASTR + ac + 8];
            ah[3] = *(const uint32_t*)&sAh[(arow + 8) * ASTR + ac + 8];
            al[0] = *(const uint32_t*)&sAl[arow * ASTR + ac];
            al[1] = *(const uint32_t*)&sAl[(arow + 8) * ASTR + ac];
            al[2] = *(const uint32_t*)&sAl[arow * ASTR + ac + 8];
            al[3] = *(const uint32_t*)&sAl[(arow + 8) * ASTR + ac + 8];
#pragma unroll
            for (int nb = 0; nb < 12; ++nb) {
                int jj = g * 96 + nb * 8 + q;
                int bc = ks * 16 + c4 * 2;
                uint32_t bh[2], bl[2];
                bh[0] = *(const uint32_t*)&sBh[jj * BSTR + bc];
                bh[1] = *(const uint32_t*)&sBh[jj * BSTR + bc + 8];
                bl[0] = *(const uint32_t*)&sBl[jj * BSTR + bc];
                bl[1] = *(const uint32_t*)&sBl[jj * BSTR + bc + 8];
                float* acc = (nb < 8) ? accRZ[nb]
                                      : ((kc < 2) ? accIN[nb - 8] : accHN[nb - 8]);
                mma16816(acc, ah, bh);
                mma16816(acc, al, bh);
                mma16816(acc, ah, bl);
            }
        }
    }

    // ---- epilogue: gates + h update (register-resident) ----
    int node_a = node0 + rb * 16 + q;
    int node_b = node_a + 8;
#pragma unroll
    for (int nb = 0; nb < 4; ++nb) {
        int d0 = g * 32 + nb * 8 + c4 * 2;
        float bi_r0 = b_ih[d0] + b_hh[d0];
        float bi_r1 = b_ih[d0 + 1] + b_hh[d0 + 1];
        float bi_z0 = b_ih[64 + d0] + b_hh[64 + d0];
        float bi_z1 = b_ih[64 + d0 + 1] + b_hh[64 + d0 + 1];
        float bin0 = b_ih[128 + d0], bin1 = b_ih[128 + d0 + 1];
        float bhn0 = b_hh[128 + d0], bhn1 = b_hh[128 + d0 + 1];
#pragma unroll
        for (int half = 0; half < 2; ++half) {
            int node = half ? node_b : node_a;
            if (node >= NN) continue;
            int ri = half * 2;     // acc regs 0,1 (row q) or 2,3 (row q+8)
            float pr0 = accRZ[nb][ri]     + bi_r0;
            float pr1 = accRZ[nb][ri + 1] + bi_r1;
            float pz0 = accRZ[nb + 4][ri]     + bi_z0;
            float pz1 = accRZ[nb + 4][ri + 1] + bi_z1;
            float in0 = accIN[nb][ri]     + bin0;
            float in1 = accIN[nb][ri + 1] + bin1;
            float hn0 = accHN[nb][ri]     + bhn0;
            float hn1 = accHN[nb][ri + 1] + bhn1;
            float r0 = 1.f / (1.f + __expf(-pr0));
            float r1 = 1.f / (1.f + __expf(-pr1));
            float z0 = 1.f / (1.f + __expf(-pz0));
            float z1 = 1.f / (1.f + __expf(-pz1));
            float n0 = tanhf(in0 + r0 * hn0);
            float n1 = tanhf(in1 + r1 * hn1);
            float2 hp = *(const float2*)&g_h[(long)node * HH + d0];
            float2 o;
            o.x = (1.f - z0) * n0 + z0 * hp.x;
            o.y = (1.f - z1) * n1 + z1 * hp.y;
            *(float2*)&g_h[(long)node * HH + d0] = o;
        }
    }
}

// ---------------- output: logits = h @ W_out, then log_softmax --------------
__global__ void __launch_bounds__(256) k_out(const float* __restrict__ wout,
                                             float* __restrict__ out) {
    __shared__ float sH[64 * HH];
    __shared__ float sW[HH * CC];
    __shared__ float sO[64 * CC];
    int tid = threadIdx.x;
    int node0 = blockIdx.x * 64;

    for (int i = tid; i < 1024; i += 256) {
        int n = i >> 4, c = i & 15;
        int node = node0 + n;
        float4 v = make_float4(0.f, 0.f, 0.f, 0.f);
        if (node < NN) v = *(const float4*)(g_h + (long)node * HH + c * 4);
        ((float4*)sH)[i] = v;
    }
    for (int i = tid; i < HH * CC; i += 256) sW[i] = wout[i];
    __syncthreads();

    int tn = tid >> 3;
    int tc = tid & 7;
    float acc[2][5];
#pragma unroll
    for (int i = 0; i < 2; ++i)
#pragma unroll
        for (int jj = 0; jj < 5; ++jj) acc[i][jj] = 0.f;
    const float* sHr = sH + tn * 2 * HH;
#pragma unroll 8
    for (int k = 0; k < HH; ++k) {
        float a0 = sHr[k], a1 = sHr[HH + k];
#pragma unroll
        for (int jj = 0; jj < 5; ++jj) {
            float w = sW[k * CC + tc + 8 * jj];
            acc[0][jj] += a0 * w;
            acc[1][jj] += a1 * w;
        }
    }
#pragma unroll
    for (int i = 0; i < 2; ++i)
#pragma unroll
        for (int jj = 0; jj < 5; ++jj)
            sO[(tn * 2 + i) * CC + tc + 8 * jj] = acc[i][jj];
    __syncthreads();

    int wid = tid >> 5, lane = tid & 31;
    for (int nn = wid; nn < 64; nn += 8) {
        int node = node0 + nn;
        if (node >= NN) continue;
        float v0 = sO[nn * CC + lane];
        float v1 = (lane < CC - 32) ? sO[nn * CC + 32 + lane] : -1e30f;
        float m = fmaxf(v0, v1);
#pragma unroll
        for (int off = 16; off > 0; off >>= 1)
            m = fmaxf(m, __shfl_xor_sync(0xFFFFFFFFu, m, off));
        float s = expf(v0 - m) + ((lane < CC - 32) ? expf(v1 - m) : 0.f);
#pragma unroll
        for (int off = 16; off > 0; off >>= 1)
            s += __shfl_xor_sync(0xFFFFFFFFu, s, off);
        float lse = m + logf(s);
        out[(long)node * CC + lane] = v0 - lse;
        if (lane < CC - 32) out[(long)node * CC + 32 + lane] = v1 - lse;
    }
}

// ---------------- launch ----------------------------------------------------
extern "C" void kernel_launch(void* const* d_in, const int* in_sizes, int n_in,
                              void* d_out, int out_size) {
    const float* x      = (const float*)d_in[0];
    const int*   ei32   = (const int*)d_in[1];
    const float* w_in   = (const float*)d_in[2];
    const float* w_out  = (const float*)d_in[3];
    const float* conv_w = (const float*)d_in[4];
    const float* w_ih   = (const float*)d_in[5];
    const float* w_hh   = (const float*)d_in[6];
    const float* b_ih   = (const float*)d_in[7];
    const float* b_hh   = (const float*)d_in[8];
    float* out = (float*)d_out;

    const int nb_scan = (NN + 2047) / 2048;       // 49
    const int eb = (EE + 255) / 256;              // 4688
    const int nodeb64 = (NN + 63) / 64;           // 1563
    const int nodeb128 = (NN + 127) / 128;        // 782

    // dtype detect + CSR build
    k_zero_misc<<<(NN + 255) / 256, 256>>>();
    k_detect<<<eb, 256>>>(ei32);
    k_hist<<<eb, 256>>>(ei32);
    k_scan1<<<nb_scan, 256>>>();
    k_scan2<<<1, 32>>>(nb_scan);
    k_scan3<<<nb_scan, 256>>>();
    k_fill<<<eb, 256>>>(ei32);

    // stacked/permuted split-bf16 weights
    k_wp<<<(LL * G3 * 128 + 255) / 256, 256>>>(conv_w, w_ih, w_hh);

    // h = x @ W_in
    k_ingemm<<<nodeb64, 256>>>(x, w_in);

    // GGNN layers (HMMA)
    for (int l = 0; l < LL; ++l) {
        k_agg<<<(NN * 32 + 255) / 256, 256>>>();
        k_gru_mma<<<nodeb128, 512>>>(b_ih, b_hh, l);
    }

    // output projection + log_softmax
    k_out<<<nodeb64, 256>>>(w_out, out);
    (void)in_sizes; (void)n_in; (void)out_size;
}

// round 10
// speedup vs baseline: 2.0195x; 2.0195x over previous
#include <cuda_runtime.h>
#include <cuda_fp16.h>
#include <cstdint>
#include <cstddef>
#include <math.h>

// Problem constants
#define NN   100000
#define FF   256
#define HH   64
#define CC   40
#define LL   4
#define EE   1200000
#define G3   192            // 3*H

// ---------------- scratch (__device__ globals; no allocation allowed) ------
__device__ __align__(16) float g_h   [NN * HH];       // hidden state
__device__ __align__(16) float g_S   [NN * HH];       // aggregated neighbor sum
// fp16 GRU weight table, stacked & column-permuted (validated layout from R8):
// G[l][jj][k], jj in [0,192), k in [0,128):
//   t=(jj%96)/32, d=(jj/96)*32+(jj%32), j=t*64+d
//   k<64 -> Wp[j][k] = sum_b conv_w[l][k][b]*w_ih[j][b] ; k>=64 -> w_hh[j][k-64]
__device__ __align__(16) __half g_G   [LL * G3 * 128];
__device__ __align__(16) __half g_WinT[64 * FF];      // W_in^T [n][k] fp16
__device__ int g_cnt   [NN];
__device__ int g_rowptr[NN + 1];
__device__ int g_cursor[NN];
__device__ int g_esrc  [EE];
__device__ int g_bsum  [64];
__device__ int g_boff  [64];
__device__ int g_fmt;          // 0 = int64 edge_index layout, 1 = int32 layout

// ---------------- mma.sync fp16 (baseline PTX, legal on compute_103) -------
__device__ __forceinline__ void mma16816(float* d, const uint32_t* a,
                                         const uint32_t* b) {
    asm volatile(
        "mma.sync.aligned.m16n8k16.row.col.f32.f16.f16.f32 "
        "{%0,%1,%2,%3}, {%4,%5,%6,%7}, {%8,%9}, {%0,%1,%2,%3};"
        : "+f"(d[0]), "+f"(d[1]), "+f"(d[2]), "+f"(d[3])
        : "r"(a[0]), "r"(a[1]), "r"(a[2]), "r"(a[3]), "r"(b[0]), "r"(b[1]));
}

__device__ __forceinline__ void cvt8h(const float* f, uint4& o) {
    unsigned int w[4];
#pragma unroll
    for (int i = 0; i < 4; ++i) {
        __half2 h2 = __floats2half2_rn(f[2 * i], f[2 * i + 1]);
        w[i] = *(unsigned int*)&h2;
    }
    o = make_uint4(w[0], w[1], w[2], w[3]);
}

// ---------------- edge dtype detection --------------------------------------
__global__ void k_zero_misc() {
    int i = blockIdx.x * blockDim.x + threadIdx.x;
    if (i < NN) g_cnt[i] = 0;
    if (i == 0) g_fmt = 0;
}

__global__ void k_detect(const int* __restrict__ ei32) {
    int i = blockIdx.x * blockDim.x + threadIdx.x;
    int v = 0;
    if (i < EE) v = ei32[2 * i + 1];
    if (__syncthreads_or(v != 0)) {
        if (threadIdx.x == 0) atomicOr(&g_fmt, 1);
    }
}

// ---------------- CSR construction -----------------------------------------
__device__ __forceinline__ int edge_src(const int* ei32, int e) {
    return g_fmt ? ei32[e] : ei32[2 * e];
}
__device__ __forceinline__ int edge_dst(const int* ei32, int e) {
    return g_fmt ? ei32[EE + e] : ei32[2 * EE + 2 * e];
}

__global__ void k_hist(const int* __restrict__ ei32) {
    int e = blockIdx.x * blockDim.x + threadIdx.x;
    if (e < EE) atomicAdd(&g_cnt[edge_dst(ei32, e)], 1);
}

__global__ void k_scan1() {
    __shared__ int red[256];
    int tid = threadIdx.x;
    int base = blockIdx.x * 2048 + tid * 8;
    int s = 0;
#pragma unroll
    for (int i = 0; i < 8; ++i) {
        int idx = base + i;
        s += (idx < NN) ? g_cnt[idx] : 0;
    }
    red[tid] = s;
    __syncthreads();
    for (int off = 128; off > 0; off >>= 1) {
        if (tid < off) red[tid] += red[tid + off];
        __syncthreads();
    }
    if (tid == 0) g_bsum[blockIdx.x] = red[0];
}

__global__ void k_scan2(int nb) {
    if (threadIdx.x == 0 && blockIdx.x == 0) {
        int run = 0;
        for (int b = 0; b < nb; ++b) {
            int t = g_bsum[b];
            g_boff[b] = run;
            run += t;
        }
        g_rowptr[NN] = run;
    }
}

__global__ void k_scan3() {
    __shared__ int sSum[256];
    int tid = threadIdx.x;
    int base = blockIdx.x * 2048 + tid * 8;
    int v[8];
    int s = 0;
#pragma unroll
    for (int i = 0; i < 8; ++i) {
        int idx = base + i;
        v[i] = (idx < NN) ? g_cnt[idx] : 0;
        s += v[i];
    }
    sSum[tid] = s;
    __syncthreads();
    for (int off = 1; off < 256; off <<= 1) {
        int t = (tid >= off) ? sSum[tid - off] : 0;
        __syncthreads();
        sSum[tid] += t;
        __syncthreads();
    }
    int excl = sSum[tid] - s + g_boff[blockIdx.x];
#pragma unroll
    for (int i = 0; i < 8; ++i) {
        int idx = base + i;
        if (idx < NN) {
            g_rowptr[idx] = excl;
            g_cursor[idx] = excl;
        }
        excl += v[i];
    }
}

__global__ void k_fill(const int* __restrict__ ei32) {
    int e = blockIdx.x * blockDim.x + threadIdx.x;
    if (e < EE) {
        int s = edge_src(ei32, e);
        int d = edge_dst(ei32, e);
        int pos = atomicAdd(&g_cursor[d], 1);
        g_esrc[pos] = s;
    }
}

// ---------------- fused weight precompute (fp16) -----------------------------
__global__ void k_wp(const float* __restrict__ conv_w,
                     const float* __restrict__ w_ih,
                     const float* __restrict__ w_hh,
                     const float* __restrict__ w_in) {
    int id = blockIdx.x * blockDim.x + threadIdx.x;
    const int NG = LL * G3 * 128;     // 98304
    if (id < NG) {
        int l = id / (G3 * 128);
        int r = id % (G3 * 128);
        int jj = r / 128;
        int k = r % 128;
        int t = (jj % 96) / 32;
        int d = (jj / 96) * 32 + (jj % 32);
        int j = t * 64 + d;
        float s;
        if (k < 64) {
            const float* cw = conv_w + (l * HH + k) * HH;
            const float* wi = w_ih + j * HH;
            s = 0.f;
#pragma unroll 8
            for (int b = 0; b < HH; ++b) s += cw[b] * wi[b];
        } else {
            s = w_hh[j * HH + (k - 64)];
        }
        g_G[id] = __float2half_rn(s);
    } else if (id < NG + 64 * FF) {
        int r = id - NG;
        int j = r / FF;         // n (0..63)
        int k = r % FF;         // k (0..255)
        g_WinT[r] = __float2half_rn(w_in[k * HH + j]);
    }
}

// ---------------- HMMA input GEMM: h = x @ W_in  [128-row tiles] ------------
#define ASTR 40
#define BSTR 36

__global__ void __launch_bounds__(512) k_ingemm_mma(const float* __restrict__ x) {
    __shared__ __half sA[128 * ASTR];   // 10240 B
    __shared__ __half sW[64 * BSTR];    //  4608 B
    int tid = threadIdx.x;
    int node0 = blockIdx.x * 128;
    int w = tid >> 5, lane = tid & 31;
    int rb = w >> 1, g = w & 1;
    int q = lane >> 2, c4 = lane & 3;

    float acc[4][4];
#pragma unroll
    for (int i = 0; i < 4; ++i)
#pragma unroll
        for (int j = 0; j < 4; ++j) acc[i][j] = 0.f;

    for (int kc = 0; kc < 8; ++kc) {
        __syncthreads();
        // stage x chunk: 128 rows x 32 k (fp32 -> fp16)
        {
            int row = tid >> 2;
            int c8 = (tid & 3) * 8;
            int node = node0 + row;
            float f[8];
            if (node < NN) {
                float4 v0 = *(const float4*)(x + (long)node * FF + kc * 32 + c8);
                float4 v1 = *(const float4*)(x + (long)node * FF + kc * 32 + c8 + 4);
                f[0] = v0.x; f[1] = v0.y; f[2] = v0.z; f[3] = v0.w;
                f[4] = v1.x; f[5] = v1.y; f[6] = v1.z; f[7] = v1.w;
            } else {
#pragma unroll
                for (int i = 0; i < 8; ++i) f[i] = 0.f;
            }
            uint4 o;
            cvt8h(f, o);
            *(uint4*)&sA[row * ASTR + c8] = o;    // 80B rows: 16B-aligned, safe
        }
        // stage W chunk: 64 n x 32 k fp16 (uint2 stores — BSTR rows are only 8B-aligned)
        for (int i = tid; i < 64 * 4; i += 512) {
            int j = i >> 2, k8 = (i & 3) * 8;
            uint4 v = *(const uint4*)(g_WinT + (size_t)j * FF + kc * 32 + k8);
            uint2* d2 = (uint2*)&sW[j * BSTR + k8];
            d2[0] = make_uint2(v.x, v.y);
            d2[1] = make_uint2(v.z, v.w);
        }
        __syncthreads();

        int arow = rb * 16 + q;
#pragma unroll
        for (int ks = 0; ks < 2; ++ks) {
            int ac = ks * 16 + c4 * 2;
            uint32_t a[4];
            a[0] = *(const uint32_t*)&sA[arow * ASTR + ac];
            a[1] = *(const uint32_t*)&sA[(arow + 8) * ASTR + ac];
            a[2] = *(const uint32_t*)&sA[arow * ASTR + ac + 8];
            a[3] = *(const uint32_t*)&sA[(arow + 8) * ASTR + ac + 8];
#pragma unroll
            for (int nb = 0; nb < 4; ++nb) {
                int jj = g * 32 + nb * 8 + q;
                uint32_t b[2];
                b[0] = *(const uint32_t*)&sW[jj * BSTR + ac];
                b[1] = *(const uint32_t*)&sW[jj * BSTR + ac + 8];
                mma16816(acc[nb], a, b);
            }
        }
    }

    // epilogue: write h
    int node_a = node0 + rb * 16 + q;
#pragma unroll
    for (int nb = 0; nb < 4; ++nb) {
        int d0 = g * 32 + nb * 8 + c4 * 2;
#pragma unroll
        for (int half = 0; half < 2; ++half) {
            int node = node_a + half * 8;
            if (node >= NN) continue;
            int ri = half * 2;
            float2 o = make_float2(acc[nb][ri], acc[nb][ri + 1]);
            *(float2*)&g_h[(long)node * HH + d0] = o;
        }
    }
}

// ---------------- aggregation: S[v] = sum_{e:dst=v} h[src[e]] ---------------
__global__ void k_agg() {
    int warp = (blockIdx.x * blockDim.x + threadIdx.x) >> 5;
    int lane = threadIdx.x & 31;
    if (warp >= NN) return;
    int beg = g_rowptr[warp], end = g_rowptr[warp + 1];
    float a0 = 0.f, a1 = 0.f, b0 = 0.f, b1 = 0.f;
    int e = beg;
    for (; e + 1 < end; e += 2) {
        int s0 = g_esrc[e], s1 = g_esrc[e + 1];
        const float* h0 = g_h + (long)s0 * HH;
        const float* h1 = g_h + (long)s1 * HH;
        a0 += h0[lane];      a1 += h0[lane + 32];
        b0 += h1[lane];      b1 += h1[lane + 32];
    }
    if (e < end) {
        const float* h0 = g_h + (long)g_esrc[e] * HH;
        a0 += h0[lane];      a1 += h0[lane + 32];
    }
    g_S[warp * HH + lane]      = a0 + b0;
    g_S[warp * HH + lane + 32] = a1 + b1;
}

// ---------------- HMMA GRU layer (1-term fp16) -------------------------------
// 128-node tile, 512 threads (16 warps). A = [S | h] (K=128), B = g_G table.
// Warp w: rows rb*16..+15 (rb=w>>1), col group g=w&1 (96 GEMM cols).
// nb 0-3: r, 4-7: z, 8-11: n (IN accumulated on S k-chunks, HN on h k-chunks).
__global__ void __launch_bounds__(512) k_gru_mma(const float* __restrict__ b_ih,
                                                 const float* __restrict__ b_hh,
                                                 int layer) {
    __shared__ __half sA[128 * ASTR];   // 10240 B
    __shared__ __half sB[G3 * BSTR];    // 13824 B
    int tid = threadIdx.x;
    int node0 = blockIdx.x * 128;

    int w = tid >> 5, lane = tid & 31;
    int rb = w >> 1, g = w & 1;
    int q = lane >> 2, c4 = lane & 3;

    float accRZ[8][4], accIN[4][4], accHN[4][4];
#pragma unroll
    for (int i = 0; i < 8; ++i)
#pragma unroll
        for (int j = 0; j < 4; ++j) accRZ[i][j] = 0.f;
#pragma unroll
    for (int i = 0; i < 4; ++i)
#pragma unroll
        for (int j = 0; j < 4; ++j) { accIN[i][j] = 0.f; accHN[i][j] = 0.f; }

    const __half* GT = g_G + (size_t)layer * G3 * 128;

    for (int kc = 0; kc < 4; ++kc) {
        __syncthreads();
        // ---- stage A chunk: rows 0..127, cols kc*32..+31 of [S|h] ----
        {
            int row = tid >> 2;
            int c8 = (tid & 3) * 8;
            int node = node0 + row;
            float f[8];
            const float* src = (kc < 2) ? g_S : g_h;
            int cb = (kc & 1) * 32 + c8;
            if (node < NN) {
                float4 v0 = *(const float4*)(src + (long)node * HH + cb);
                float4 v1 = *(const float4*)(src + (long)node * HH + cb + 4);
                f[0] = v0.x; f[1] = v0.y; f[2] = v0.z; f[3] = v0.w;
                f[4] = v1.x; f[5] = v1.y; f[6] = v1.z; f[7] = v1.w;
            } else {
#pragma unroll
                for (int i = 0; i < 8; ++i) f[i] = 0.f;
            }
            uint4 o;
            cvt8h(f, o);
            *(uint4*)&sA[row * ASTR + c8] = o;    // 80B rows: 16B-aligned, safe
        }
        // ---- stage B chunk: 192 cols x 32 k (uint2 stores for alignment) ----
        for (int i = tid; i < G3 * 4; i += 512) {
            int j = i >> 2, k8 = (i & 3) * 8;
            uint4 v = *(const uint4*)(GT + (size_t)j * 128 + kc * 32 + k8);
            uint2* d2 = (uint2*)&sB[j * BSTR + k8];
            d2[0] = make_uint2(v.x, v.y);
            d2[1] = make_uint2(v.z, v.w);
        }
        __syncthreads();

        int arow = rb * 16 + q;
#pragma unroll
        for (int ks = 0; ks < 2; ++ks) {
            int ac = ks * 16 + c4 * 2;
            uint32_t a[4];
            a[0] = *(const uint32_t*)&sA[arow * ASTR + ac];
            a[1] = *(const uint32_t*)&sA[(arow + 8) * ASTR + ac];
            a[2] = *(const uint32_t*)&sA[arow * ASTR + ac + 8];
            a[3] = *(const uint32_t*)&sA[(arow + 8) * ASTR + ac + 8];
#pragma unroll
            for (int nb = 0; nb < 12; ++nb) {
                int jj = g * 96 + nb * 8 + q;
                uint32_t b[2];
                b[0] = *(const uint32_t*)&sB[jj * BSTR + ac];
                b[1] = *(const uint32_t*)&sB[jj * BSTR + ac + 8];
                float* acc = (nb < 8) ? accRZ[nb]
                                      : ((kc < 2) ? accIN[nb - 8] : accHN[nb - 8]);
                mma16816(acc, a, b);
            }
        }
    }

    // ---- epilogue: gates + h update (register-resident) ----
    int node_a = node0 + rb * 16 + q;
#pragma unroll
    for (int nb = 0; nb < 4; ++nb) {
        int d0 = g * 32 + nb * 8 + c4 * 2;
        float bi_r0 = b_ih[d0] + b_hh[d0];
        float bi_r1 = b_ih[d0 + 1] + b_hh[d0 + 1];
        float bi_z0 = b_ih[64 + d0] + b_hh[64 + d0];
        float bi_z1 = b_ih[64 + d0 + 1] + b_hh[64 + d0 + 1];
        float bin0 = b_ih[128 + d0], bin1 = b_ih[128 + d0 + 1];
        float bhn0 = b_hh[128 + d0], bhn1 = b_hh[128 + d0 + 1];
#pragma unroll
        for (int half = 0; half < 2; ++half) {
            int node = node_a + half * 8;
            if (node >= NN) continue;
            int ri = half * 2;
            float pr0 = accRZ[nb][ri]     + bi_r0;
            float pr1 = accRZ[nb][ri + 1] + bi_r1;
            float pz0 = accRZ[nb + 4][ri]     + bi_z0;
            float pz1 = accRZ[nb + 4][ri + 1] + bi_z1;
            float in0 = accIN[nb][ri]     + bin0;
            float in1 = accIN[nb][ri + 1] + bin1;
            float hn0 = accHN[nb][ri]     + bhn0;
            float hn1 = accHN[nb][ri + 1] + bhn1;
            float r0 = 1.f / (1.f + __expf(-pr0));
            float r1 = 1.f / (1.f + __expf(-pr1));
            float z0 = 1.f / (1.f + __expf(-pz0));
            float z1 = 1.f / (1.f + __expf(-pz1));
            float n0 = tanhf(in0 + r0 * hn0);
            float n1 = tanhf(in1 + r1 * hn1);
            float2 hp = *(const float2*)&g_h[(long)node * HH + d0];
            float2 o;
            o.x = (1.f - z0) * n0 + z0 * hp.x;
            o.y = (1.f - z1) * n1 + z1 * hp.y;
            *(float2*)&g_h[(long)node * HH + d0] = o;
        }
    }
}

// ---------------- output: logits = h @ W_out, then log_softmax --------------
__global__ void __launch_bounds__(256) k_out(const float* __restrict__ wout,
                                             float* __restrict__ out) {
    __shared__ float sH[64 * HH];
    __shared__ float sW[HH * CC];
    __shared__ float sO[64 * CC];
    int tid = threadIdx.x;
    int node0 = blockIdx.x * 64;

    for (int i = tid; i < 1024; i += 256) {
        int n = i >> 4, c = i & 15;
        int node = node0 + n;
        float4 v = make_float4(0.f, 0.f, 0.f, 0.f);
        if (node < NN) v = *(const float4*)(g_h + (long)node * HH + c * 4);
        ((float4*)sH)[i] = v;
    }
    for (int i = tid; i < HH * CC; i += 256) sW[i] = wout[i];
    __syncthreads();

    int tn = tid >> 3;
    int tc = tid & 7;
    float acc[2][5];
#pragma unroll
    for (int i = 0; i < 2; ++i)
#pragma unroll
        for (int jj = 0; jj < 5; ++jj) acc[i][jj] = 0.f;
    const float* sHr = sH + tn * 2 * HH;
#pragma unroll 8
    for (int k = 0; k < HH; ++k) {
        float a0 = sHr[k], a1 = sHr[HH + k];
#pragma unroll
        for (int jj = 0; jj < 5; ++jj) {
            float w = sW[k * CC + tc + 8 * jj];
            acc[0][jj] += a0 * w;
            acc[1][jj] += a1 * w;
        }
    }
#pragma unroll
    for (int i = 0; i < 2; ++i)
#pragma unroll
        for (int jj = 0; jj < 5; ++jj)
            sO[(tn * 2 + i) * CC + tc + 8 * jj] = acc[i][jj];
    __syncthreads();

    int wid = tid >> 5, lane = tid & 31;
    for (int nn = wid; nn < 64; nn += 8) {
        int node = node0 + nn;
        if (node >= NN) continue;
        float v0 = sO[nn * CC + lane];
        float v1 = (lane < CC - 32) ? sO[nn * CC + 32 + lane] : -1e30f;
        float m = fmaxf(v0, v1);
#pragma unroll
        for (int off = 16; off > 0; off >>= 1)
            m = fmaxf(m, __shfl_xor_sync(0xFFFFFFFFu, m, off));
        float s = expf(v0 - m) + ((lane < CC - 32) ? expf(v1 - m) : 0.f);
#pragma unroll
        for (int off = 16; off > 0; off >>= 1)
            s += __shfl_xor_sync(0xFFFFFFFFu, s, off);
        float lse = m + logf(s);
        out[(long)node * CC + lane] = v0 - lse;
        if (lane < CC - 32) out[(long)node * CC + 32 + lane] = v1 - lse;
    }
}

// ---------------- launch ----------------------------------------------------
extern "C" void kernel_launch(void* const* d_in, const int* in_sizes, int n_in,
                              void* d_out, int out_size) {
    const float* x      = (const float*)d_in[0];
    const int*   ei32   = (const int*)d_in[1];
    const float* w_in   = (const float*)d_in[2];
    const float* w_out  = (const float*)d_in[3];
    const float* conv_w = (const float*)d_in[4];
    const float* w_ih   = (const float*)d_in[5];
    const float* w_hh   = (const float*)d_in[6];
    const float* b_ih   = (const float*)d_in[7];
    const float* b_hh   = (const float*)d_in[8];
    float* out = (float*)d_out;

    const int nb_scan = (NN + 2047) / 2048;       // 49
    const int eb = (EE + 255) / 256;              // 4688
    const int nodeb64 = (NN + 63) / 64;           // 1563
    const int nodeb128 = (NN + 127) / 128;        // 782

    // dtype detect + CSR build
    k_zero_misc<<<(NN + 255) / 256, 256>>>();
    k_detect<<<eb, 256>>>(ei32);
    k_hist<<<eb, 256>>>(ei32);
    k_scan1<<<nb_scan, 256>>>();
    k_scan2<<<1, 32>>>(nb_scan);
    k_scan3<<<nb_scan, 256>>>();
    k_fill<<<eb, 256>>>(ei32);

    // fp16 weight tables (fused GRU table + W_in^T)
    k_wp<<<(LL * G3 * 128 + 64 * FF + 255) / 256, 256>>>(conv_w, w_ih, w_hh, w_in);

    // h = x @ W_in  (HMMA fp16)
    k_ingemm_mma<<<nodeb128, 512>>>(x);

    // GGNN layers (HMMA fp16, 1-term)
    for (int l = 0; l < LL; ++l) {
        k_agg<<<(NN * 32 + 255) / 256, 256>>>();
        k_gru_mma<<<nodeb128, 512>>>(b_ih, b_hh, l);
    }

    // output projection + log_softmax
    k_out<<<nodeb64, 256>>>(w_out, out);
    (void)in_sizes; (void)n_in; (void)out_size;
}